// round 9
// baseline (speedup 1.0000x reference)
#include <cuda_runtime.h>

// GRU-D on GB300 (sm_103a). Fixed problem sizes:
#define BATCH 1024
#define LTRUE 96
#define LPRED 24
#define LALL  120
#define NF    64
#define HID   128

typedef unsigned long long ull;

// ---------------------------------------------------------------------------
// Packed fp32x2 helpers.
// ---------------------------------------------------------------------------
#define FMA2(acc, a, b) \
    asm("fma.rn.f32x2 %0, %1, %2, %0;" : "+l"(acc) : "l"(a), "l"(b))

__device__ __forceinline__ ull pack_dup(float v) {
    ull r; asm("mov.b64 %0, {%1, %1};" : "=l"(r) : "f"(v)); return r;
}
__device__ __forceinline__ ull pack_pair(float a, float b) {
    ull r; asm("mov.b64 %0, {%1, %2};" : "=l"(r) : "f"(a), "f"(b)); return r;
}
__device__ __forceinline__ void unpack2(ull p, float& a, float& b) {
    asm("mov.b64 {%0, %1}, %2;" : "=f"(a), "=f"(b) : "l"(p));
}
__device__ __forceinline__ ull mul2(ull a, ull b) {
    ull r; asm("mul.rn.f32x2 %0, %1, %2;" : "=l"(r) : "l"(a), "l"(b)); return r;
}
__device__ __forceinline__ ull add2(ull a, ull b) {
    ull r; asm("add.rn.f32x2 %0, %1, %2;" : "=l"(r) : "l"(a), "l"(b)); return r;
}

// ---------------------------------------------------------------------------
// Packed weight tables, [kk*128 + j], kk = k/2:
//   g_WRp/g_WZp/g_WN1p : {w(2kk), c(2kk), w(2kk+1), c(2kk+1)}  streamed (LDG)
//   g_WN2p             : {wN2(2kk), wN2(2kk+1)}                smem-resident
// w = merged recurrent weight, c = input-side col
//   (k<64 -> x_in col k ; k>=64 -> mask col 128+k).
// ---------------------------------------------------------------------------
__device__ float4 g_WRp [64 * 128];
__device__ float4 g_WZp [64 * 128];
__device__ float4 g_WN1p[64 * 128];
__device__ float2 g_WN2p[64 * 128];
__device__ float  g_rep[(size_t)BATCH * LPRED * HID];

// Shared memory layout (float offsets)
#define OFF_TN2   0          // float2[8192] = 16384 floats (64 KB)
#define OFF_SH    16384      // s_h  [k][8]  1024
#define OFF_SIN   17408      // s_in [k][8]  1024
#define OFF_PART  18432      // ull[4*2304] = 18432 floats (pad stride 18, 16B-aligned)
#define OFF_SDT   36864      // dt [r][120]  960
#define OFF_BIAS  37824      // 512
#define SMEM_FLOATS 38336
#define SMEM_BYTES (SMEM_FLOATS * 4)    // 153344 B

// Projection overlay (tables dead after the loop)
#define OFFP_REP 0           // 8*24*128 = 24576 floats
#define OFFP_WP  24576       // 64*129 = 8256
#define OFFP_BP  32832       // 64

#define PSTRIDE 2304         // per-gate partial stride in ull (128*18)

// ---------------------------------------------------------------------------
__global__ void grud_prep_kernel(const float* __restrict__ W_ih,
                                 const float* __restrict__ W_hh)
{
    int idx = blockIdx.x * blockDim.x + threadIdx.x;
    if (idx >= 64 * 128) return;
    int kk = idx >> 7;
    int j  = idx & 127;
    int k0 = 2 * kk, k1 = 2 * kk + 1;
    int c0 = (k0 < 64) ? k0 : (128 + k0);
    int c1 = (k1 < 64) ? k1 : (128 + k1);

    float4 r4;
    r4.x = W_ih[j * 256 + 64 + k0] + W_hh[j * 128 + k0];
    r4.y = W_ih[j * 256 + c0];
    r4.z = W_ih[j * 256 + 64 + k1] + W_hh[j * 128 + k1];
    r4.w = W_ih[j * 256 + c1];
    g_WRp[idx] = r4;

    float4 z4;
    z4.x = W_ih[(128 + j) * 256 + 64 + k0] + W_hh[(128 + j) * 128 + k0];
    z4.y = W_ih[(128 + j) * 256 + c0];
    z4.z = W_ih[(128 + j) * 256 + 64 + k1] + W_hh[(128 + j) * 128 + k1];
    z4.w = W_ih[(128 + j) * 256 + c1];
    g_WZp[idx] = z4;

    float4 n4;
    n4.x = W_ih[(256 + j) * 256 + 64 + k0];
    n4.y = W_ih[(256 + j) * 256 + c0];
    n4.z = W_ih[(256 + j) * 256 + 64 + k1];
    n4.w = W_ih[(256 + j) * 256 + c1];
    g_WN1p[idx] = n4;

    float2 m2;
    m2.x = W_hh[(256 + j) * 128 + k0];
    m2.y = W_hh[(256 + j) * 128 + k1];
    g_WN2p[idx] = m2;
}

// ---------------------------------------------------------------------------
// Streamed-gate GEMM over one K-quarter (32 k = 16 kk). Lane l covers
// j = l + 32*jj. acc[jj][pair] accumulates w*h + c*x for 4 row pairs.
// wA (first kk) is preloaded by the caller BEFORE the S1 barrier so the
// initial LDG latency hides behind barrier arrival skew.
// ---------------------------------------------------------------------------
__device__ __forceinline__ void gemm_stream_q(ull acc[4][4],
                                              const float4* __restrict__ T,
                                              float4 wA[4],
                                              int q, int l,
                                              const float* s_h,
                                              const float* s_in)
{
    const float4* Tp = T + ((q * 16) << 7) + l;
    float4 wB[4];

    #pragma unroll
    for (int kk = 0; kk < 16; kk++) {
        if (kk < 15) {
            #pragma unroll
            for (int jj = 0; jj < 4; jj++)
                wB[jj] = __ldg(Tp + (kk + 1) * 128 + jj * 32);
        }
        const int k0 = (q * 16 + kk) * 2;
        ulonglong2 hA0 = *(const ulonglong2*)(s_h  + k0 * 8);
        ulonglong2 hB0 = *(const ulonglong2*)(s_h  + k0 * 8 + 4);
        ulonglong2 xA0 = *(const ulonglong2*)(s_in + k0 * 8);
        ulonglong2 xB0 = *(const ulonglong2*)(s_in + k0 * 8 + 4);
        ulonglong2 hA1 = *(const ulonglong2*)(s_h  + k0 * 8 + 8);
        ulonglong2 hB1 = *(const ulonglong2*)(s_h  + k0 * 8 + 12);
        ulonglong2 xA1 = *(const ulonglong2*)(s_in + k0 * 8 + 8);
        ulonglong2 xB1 = *(const ulonglong2*)(s_in + k0 * 8 + 12);
        #pragma unroll
        for (int jj = 0; jj < 4; jj++) {
            float4 w = wA[jj];
            ull w0 = pack_dup(w.x), c0 = pack_dup(w.y);
            FMA2(acc[jj][0], w0, hA0.x); FMA2(acc[jj][1], w0, hA0.y);
            FMA2(acc[jj][2], w0, hB0.x); FMA2(acc[jj][3], w0, hB0.y);
            FMA2(acc[jj][0], c0, xA0.x); FMA2(acc[jj][1], c0, xA0.y);
            FMA2(acc[jj][2], c0, xB0.x); FMA2(acc[jj][3], c0, xB0.y);
            ull w1 = pack_dup(w.z), c1 = pack_dup(w.w);
            FMA2(acc[jj][0], w1, hA1.x); FMA2(acc[jj][1], w1, hA1.y);
            FMA2(acc[jj][2], w1, hB1.x); FMA2(acc[jj][3], w1, hB1.y);
            FMA2(acc[jj][0], c1, xA1.x); FMA2(acc[jj][1], c1, xA1.y);
            FMA2(acc[jj][2], c1, xB1.x); FMA2(acc[jj][3], c1, xB1.y);
        }
        #pragma unroll
        for (int jj = 0; jj < 4; jj++) wA[jj] = wB[jj];
    }
}

// N2 gate (h-only, smem-resident table).
__device__ __forceinline__ void gemm_n2_q(ull acc[4][4],
                                          const float2* __restrict__ sT,
                                          int q, int l, const float* s_h)
{
    #pragma unroll
    for (int i = 0; i < 16; i++) {
        const int kk = q * 16 + i;
        const int k0 = kk * 2;
        ulonglong2 hA0 = *(const ulonglong2*)(s_h + k0 * 8);
        ulonglong2 hB0 = *(const ulonglong2*)(s_h + k0 * 8 + 4);
        ulonglong2 hA1 = *(const ulonglong2*)(s_h + k0 * 8 + 8);
        ulonglong2 hB1 = *(const ulonglong2*)(s_h + k0 * 8 + 12);
        #pragma unroll
        for (int jj = 0; jj < 4; jj++) {
            float2 w = sT[(kk << 7) + l + 32 * jj];
            ull w0 = pack_dup(w.x), w1 = pack_dup(w.y);
            FMA2(acc[jj][0], w0, hA0.x); FMA2(acc[jj][1], w0, hA0.y);
            FMA2(acc[jj][2], w0, hB0.x); FMA2(acc[jj][3], w0, hB0.y);
            FMA2(acc[jj][0], w1, hA1.x); FMA2(acc[jj][1], w1, hA1.y);
            FMA2(acc[jj][2], w1, hB1.x); FMA2(acc[jj][3], w1, hB1.y);
        }
    }
}

// ---------------------------------------------------------------------------
// Main kernel: 128 blocks x 512 threads, 8 batch rows per block.
// Warp wid: gate g = wid>>2, K-quarter q = wid&3 (one warp of each gate per
// SMSP). Lane l covers j = l+32*jj. Partials exchanged in smem layout
// [gate][j][pair][q] (stride 18 ull -> 16B-aligned, conflict-free LDS.128);
// thread (jr = tid&127, pr = tid>>7) owns h row-pair (jr, rows 2pr,2pr+1).
// ---------------------------------------------------------------------------
__global__ __launch_bounds__(512, 1)
void grud_main_kernel(const float* __restrict__ tp_pred,
                      const float* __restrict__ X,
                      const float* __restrict__ tp_true,
                      const float* __restrict__ mask,
                      const float* __restrict__ Wh_dec,
                      const float* __restrict__ bh_dec,
                      const float* __restrict__ Wx_dec,
                      const float* __restrict__ bx_dec,
                      const float* __restrict__ b_ih,
                      const float* __restrict__ b_hh,
                      const float* __restrict__ Wp,
                      const float* __restrict__ bp,
                      float* __restrict__ out)
{
    extern __shared__ float smem[];
    float2* sTN2  = (float2*)(smem + OFF_TN2);
    float*  s_h   = smem + OFF_SH;
    float*  s_in  = smem + OFF_SIN;
    ull*    s_part = (ull*)(smem + OFF_PART);
    float*  s_dt  = smem + OFF_SDT;
    float*  s_bias = smem + OFF_BIAS;

    const int tid = threadIdx.x;
    const int wid = tid >> 5, l = tid & 31;
    const int g   = wid >> 2, q = wid & 3;
    const int jr  = tid & 127, pr = tid >> 7;
    const int b0  = blockIdx.x * 8;

    // ---- stage N2 table ----
    for (int i = tid; i < 64 * 128; i += 512) sTN2[i] = g_WN2p[i];

    // ---- biases: s_bias[gate*128 + j] ----
    {
        int bg = tid >> 7, bj = tid & 127;
        float ub;
        if      (bg == 0) ub = b_ih[bj]       + b_hh[bj];
        else if (bg == 1) ub = b_ih[128 + bj] + b_hh[128 + bj];
        else if (bg == 2) ub = b_ih[256 + bj];
        else              ub = b_hh[256 + bj];
        s_bias[bg * 128 + bj] = ub;
    }

    // ---- decay constants for own j (jr) ----
    float S = 0.0f;
    #pragma unroll 8
    for (int n = 0; n < NF; n++) S += Wh_dec[jr * NF + n];
    const float bh = bh_dec[jr];

    // ---- feature slot: one (row, feature) per thread ----
    const int rf = tid >> 6;          // 0..7
    const int nf = tid & 63;
    const float wxd = Wx_dec[nf * 64 + nf];
    const float bx  = bx_dec[nf];
    const float* Xp = X    + (size_t)(b0 + rf) * LTRUE * NF + nf;
    const float* Mp = mask + (size_t)(b0 + rf) * LTRUE * NF + nf;

    float sum = 0.0f, cnt = (float)LPRED;
    for (int t = 0; t < LTRUE; t++) {
        float m = Mp[t * NF], x = Xp[t * NF];
        sum += x * (1.0f - m);  cnt += 1.0f - m;
    }
    const float mu = sum / fmaxf(cnt, 1.0f);
    float xl = Xp[0];                 // LOCF state

    // ---- dt table ----
    for (int it = tid; it < 8 * LALL; it += 512) {
        int r = it / LALL, t = it % LALL;
        int b = b0 + r;
        float d = 0.0f;
        if (t > 0) {
            float a = (t     < LTRUE) ? tp_true[b * LTRUE + t]
                                      : tp_pred[b * LPRED + (t - LTRUE)];
            float p = (t - 1 < LTRUE) ? tp_true[b * LTRUE + (t - 1)]
                                      : tp_pred[b * LPRED + (t - 1 - LTRUE)];
            d = a - p;
        }
        s_dt[r * LALL + t] = d;
    }

    ull h = 0ull;                     // own row pair (jr; rows 2pr, 2pr+1)
    float xv_buf = xl;                // X[t=0] prefetch (== Xp[0])
    float mv_buf = Mp[0];
    __syncthreads();

    for (int t = 0; t < LALL; t++) {
        // ======== phase A: feature slot + decay own pair ========
        {
            float xv = (t < LTRUE) ? xv_buf : 0.0f;
            float mv = (t < LTRUE) ? mv_buf : 0.0f;
            // prefetch t+1 (in flight across S1 + GEMM)
            if (t + 1 < LTRUE) {
                xv_buf = Xp[(t + 1) * NF];
                mv_buf = Mp[(t + 1) * NF];
            }
            float d  = s_dt[rf * LALL + t];
            float gx = __expf(-fmaxf(fmaf(d, wxd, bx), 0.0f));
            xl = (mv != 0.0f) ? xl : xv;
            float xh = gx * xl + (1.0f - gx) * mu;
            float xi = mv * xv + (1.0f - mv) * xh;
            s_in[nf * 8 + rf]        = xi;
            s_in[(64 + nf) * 8 + rf] = mv;
        }
        {
            float d0 = s_dt[(2 * pr    ) * LALL + t];
            float d1 = s_dt[(2 * pr + 1) * LALL + t];
            float gh0 = __expf(-fmaxf(fmaf(d0, S, bh), 0.0f));
            float gh1 = __expf(-fmaxf(fmaf(d1, S, bh), 0.0f));
            h = mul2(h, pack_pair(gh0, gh1));
            *(ull*)(s_h + jr * 8 + 2 * pr) = h;
            if (t >= LTRUE) {
                int tt = t - LTRUE;
                float f0, f1; unpack2(h, f0, f1);
                g_rep[((size_t)(b0 + 2 * pr    ) * LPRED + tt) * HID + jr] = f0;
                g_rep[((size_t)(b0 + 2 * pr + 1) * LPRED + tt) * HID + jr] = f1;
            }
        }

        // ---- hoisted weight prefetch (kk=0) for streamed gates ----
        float4 wA[4];
        if (g < 3) {
            const float4* T = (g == 0) ? g_WRp : (g == 1) ? g_WZp : g_WN1p;
            const float4* Tp = T + ((q * 16) << 7) + l;
            #pragma unroll
            for (int jj = 0; jj < 4; jj++) wA[jj] = __ldg(Tp + jj * 32);
        }
        __syncthreads();   // S1

        // ======== phase B: K-quarter GEMM per warp ========
        {
            ull acc[4][4];
            #pragma unroll
            for (int jj = 0; jj < 4; jj++)
                #pragma unroll
                for (int p = 0; p < 4; p++) acc[jj][p] = 0ull;

            if (g < 3) {
                const float4* T = (g == 0) ? g_WRp : (g == 1) ? g_WZp : g_WN1p;
                gemm_stream_q(acc, T, wA, q, l, s_h, s_in);
            } else {
                gemm_n2_q(acc, sTN2, q, l, s_h);
            }
            // layout [gate][j][pair][q], stride 18 ull per j
            #pragma unroll
            for (int jj = 0; jj < 4; jj++) {
                int jdx = l + 32 * jj;
                #pragma unroll
                for (int p = 0; p < 4; p++)
                    s_part[g * PSTRIDE + jdx * 18 + p * 4 + q] = acc[jj][p];
            }
        }
        __syncthreads();   // S2

        // ======== phase C: reduce partials + activation (all threads) ========
        {
            const int base = jr * 18 + pr * 4;   // 16B-aligned
            ulonglong2 r01 = ((const ulonglong2*)(s_part + 0 * PSTRIDE + base))[0];
            ulonglong2 r23 = ((const ulonglong2*)(s_part + 0 * PSTRIDE + base))[1];
            ulonglong2 z01 = ((const ulonglong2*)(s_part + 1 * PSTRIDE + base))[0];
            ulonglong2 z23 = ((const ulonglong2*)(s_part + 1 * PSTRIDE + base))[1];
            ulonglong2 n01 = ((const ulonglong2*)(s_part + 2 * PSTRIDE + base))[0];
            ulonglong2 n23 = ((const ulonglong2*)(s_part + 2 * PSTRIDE + base))[1];
            ulonglong2 m01 = ((const ulonglong2*)(s_part + 3 * PSTRIDE + base))[0];
            ulonglong2 m23 = ((const ulonglong2*)(s_part + 3 * PSTRIDE + base))[1];

            ull sR  = add2(add2(r01.x, r01.y), add2(r23.x, r23.y));
            ull sZ  = add2(add2(z01.x, z01.y), add2(z23.x, z23.y));
            ull sN1 = add2(add2(n01.x, n01.y), add2(n23.x, n23.y));
            ull sN2 = add2(add2(m01.x, m01.y), add2(m23.x, m23.y));

            sR  = add2(sR,  pack_dup(s_bias[jr]));
            sZ  = add2(sZ,  pack_dup(s_bias[128 + jr]));
            sN1 = add2(sN1, pack_dup(s_bias[256 + jr]));
            sN2 = add2(sN2, pack_dup(s_bias[384 + jr]));

            float ra, rb, za, zb, n1x, n1y, n2x, n2y, hx, hy;
            unpack2(sR, ra, rb);
            unpack2(sZ, za, zb);
            unpack2(sN1, n1x, n1y);
            unpack2(sN2, n2x, n2y);
            unpack2(h, hx, hy);
            float rg0 = 1.0f / (1.0f + __expf(-ra));
            float rg1 = 1.0f / (1.0f + __expf(-rb));
            float zg0 = 1.0f / (1.0f + __expf(-za));
            float zg1 = 1.0f / (1.0f + __expf(-zb));
            float p0  = fmaf(rg0, n2x, n1x);
            float p1  = fmaf(rg1, n2y, n1y);
            float ng0 = 1.0f - 2.0f / (1.0f + __expf(2.0f * p0));
            float ng1 = 1.0f - 2.0f / (1.0f + __expf(2.0f * p1));
            float h0  = (1.0f - zg0) * ng0 + zg0 * hx;
            float h1  = (1.0f - zg1) * ng1 + zg1 * hy;
            h = pack_pair(h0, h1);
        }
    }

    // ======== fused projection: out = rep @ Wp^T + bp (own 8 rows) ========
    __syncthreads();                  // recurrent loop done; tables dead
    {
        const float4* rep4 = (const float4*)(g_rep + (size_t)b0 * LPRED * HID);
        float4* sRep4 = (float4*)(smem + OFFP_REP);
        for (int i = tid; i < 8 * LPRED * HID / 4; i += 512)
            sRep4[i] = rep4[i];
        for (int i = tid; i < 64 * 128; i += 512) {
            int n = i >> 7, jj = i & 127;
            smem[OFFP_WP + n * 129 + jj] = Wp[i];
        }
        if (tid < 64) smem[OFFP_BP + tid] = bp[tid];
    }
    __syncthreads();
    #pragma unroll 1
    for (int qq = 0; qq < 24; qq++) {
        int o   = tid + 512 * qq;             // 0..12287
        int row = o / 1536;
        int rem = o - row * 1536;
        int tp  = rem >> 6, n = rem & 63;
        float acc = smem[OFFP_BP + n];
        const float* rp = smem + OFFP_REP + (row * LPRED + tp) * HID;
        const float* wp = smem + OFFP_WP + n * 129;
        #pragma unroll 8
        for (int jj = 0; jj < 128; jj++)
            acc = fmaf(rp[jj], wp[jj], acc);
        out[((size_t)(b0 + row) * LPRED + tp) * 64 + n] = acc;
    }
}

// ---------------------------------------------------------------------------
extern "C" void kernel_launch(void* const* d_in, const int* in_sizes, int n_in,
                              void* d_out, int out_size)
{
    const float* tp_pred = (const float*)d_in[0];
    const float* X       = (const float*)d_in[1];
    const float* tp_true = (const float*)d_in[2];
    const float* mask    = (const float*)d_in[3];
    const float* Wh_dec  = (const float*)d_in[4];
    const float* bh_dec  = (const float*)d_in[5];
    const float* Wx_dec  = (const float*)d_in[6];
    const float* bx_dec  = (const float*)d_in[7];
    const float* W_ih    = (const float*)d_in[8];
    const float* W_hh    = (const float*)d_in[9];
    const float* b_ih    = (const float*)d_in[10];
    const float* b_hh    = (const float*)d_in[11];
    const float* Wp      = (const float*)d_in[12];
    const float* bp      = (const float*)d_in[13];
    float* out = (float*)d_out;

    cudaFuncSetAttribute(grud_main_kernel,
                         cudaFuncAttributeMaxDynamicSharedMemorySize,
                         SMEM_BYTES);

    grud_prep_kernel<<<32, 256>>>(W_ih, W_hh);
    grud_main_kernel<<<BATCH / 8, 512, SMEM_BYTES>>>(
        tp_pred, X, tp_true, mask,
        Wh_dec, bh_dec, Wx_dec, bx_dec, b_ih, b_hh,
        Wp, bp, out);
}

// round 12
// speedup vs baseline: 1.0134x; 1.0134x over previous
#include <cuda_runtime.h>

// GRU-D on GB300 (sm_103a). Fixed problem sizes:
#define BATCH 1024
#define LTRUE 96
#define LPRED 24
#define LALL  120
#define NF    64
#define HID   128

typedef unsigned long long ull;

// ---------------------------------------------------------------------------
// Packed fp32x2 helpers.
// ---------------------------------------------------------------------------
#define FMA2(acc, a, b) \
    asm("fma.rn.f32x2 %0, %1, %2, %0;" : "+l"(acc) : "l"(a), "l"(b))

__device__ __forceinline__ ull pack_dup(float v) {
    ull r; asm("mov.b64 %0, {%1, %1};" : "=l"(r) : "f"(v)); return r;
}
__device__ __forceinline__ ull pack_pair(float a, float b) {
    ull r; asm("mov.b64 %0, {%1, %2};" : "=l"(r) : "f"(a), "f"(b)); return r;
}
__device__ __forceinline__ void unpack2(ull p, float& a, float& b) {
    asm("mov.b64 {%0, %1}, %2;" : "=f"(a), "=f"(b) : "l"(p));
}
__device__ __forceinline__ ull mul2(ull a, ull b) {
    ull r; asm("mul.rn.f32x2 %0, %1, %2;" : "=l"(r) : "l"(a), "l"(b)); return r;
}
__device__ __forceinline__ ull add2(ull a, ull b) {
    ull r; asm("add.rn.f32x2 %0, %1, %2;" : "=l"(r) : "l"(a), "l"(b)); return r;
}

// ---------------------------------------------------------------------------
// Packed weight tables, [kk*128 + j], kk = k/2:
//   g_WRp/g_WZp/g_WN1p : {w(2kk), c(2kk), w(2kk+1), c(2kk+1)}  streamed (LDG)
//   g_WN2p             : {wN2(2kk), wN2(2kk+1)}                smem-resident
// w = merged recurrent weight, c = input-side col
//   (k<64 -> x_in col k ; k>=64 -> mask col 128+k).
// ---------------------------------------------------------------------------
__device__ float4 g_WRp [64 * 128];
__device__ float4 g_WZp [64 * 128];
__device__ float4 g_WN1p[64 * 128];
__device__ float2 g_WN2p[64 * 128];
__device__ float  g_rep[(size_t)BATCH * LPRED * HID];

// Shared memory layout (float offsets) — R7-proven stride-17 partials
#define OFF_TN2   0          // float2[8192] = 16384 floats (64 KB)
#define OFF_SH    16384      // s_h  [k][8]  1024
#define OFF_SIN   17408      // s_in [k][8]  1024
#define OFF_PART  18432      // ull[4*2176]  = 17408 floats (padded stride 17)
#define OFF_SDT   35840      // dt [r][120]  960
#define OFF_BIAS  36800      // 512
#define SMEM_FLOATS 37312
#define SMEM_BYTES (SMEM_FLOATS * 4)    // 149248 B

// Projection overlay (tables dead after the loop)
#define OFFP_REP 0           // 8*24*128 = 24576 floats
#define OFFP_WP  24576       // 64*129 = 8256
#define OFFP_BP  32832       // 64

#define PSTRIDE 2176         // per-gate partial stride in ull (128*17)

// ---------------------------------------------------------------------------
__global__ void grud_prep_kernel(const float* __restrict__ W_ih,
                                 const float* __restrict__ W_hh)
{
    int idx = blockIdx.x * blockDim.x + threadIdx.x;
    if (idx >= 64 * 128) return;
    int kk = idx >> 7;
    int j  = idx & 127;
    int k0 = 2 * kk, k1 = 2 * kk + 1;
    int c0 = (k0 < 64) ? k0 : (128 + k0);
    int c1 = (k1 < 64) ? k1 : (128 + k1);

    float4 r4;
    r4.x = W_ih[j * 256 + 64 + k0] + W_hh[j * 128 + k0];
    r4.y = W_ih[j * 256 + c0];
    r4.z = W_ih[j * 256 + 64 + k1] + W_hh[j * 128 + k1];
    r4.w = W_ih[j * 256 + c1];
    g_WRp[idx] = r4;

    float4 z4;
    z4.x = W_ih[(128 + j) * 256 + 64 + k0] + W_hh[(128 + j) * 128 + k0];
    z4.y = W_ih[(128 + j) * 256 + c0];
    z4.z = W_ih[(128 + j) * 256 + 64 + k1] + W_hh[(128 + j) * 128 + k1];
    z4.w = W_ih[(128 + j) * 256 + c1];
    g_WZp[idx] = z4;

    float4 n4;
    n4.x = W_ih[(256 + j) * 256 + 64 + k0];
    n4.y = W_ih[(256 + j) * 256 + c0];
    n4.z = W_ih[(256 + j) * 256 + 64 + k1];
    n4.w = W_ih[(256 + j) * 256 + c1];
    g_WN1p[idx] = n4;

    float2 m2;
    m2.x = W_hh[(256 + j) * 128 + k0];
    m2.y = W_hh[(256 + j) * 128 + k1];
    g_WN2p[idx] = m2;
}

// ---------------------------------------------------------------------------
// Streamed-gate GEMM over one K-quarter (32 k = 16 kk). Lane l covers
// j = l + 32*jj. acc[jj][pair] accumulates w*h + c*x for 4 row pairs.
// DISTANCE-2 software pipeline: caller preloads wA (kk=0) and wB (kk=1)
// BEFORE the S1 barrier; loop issues kk+2 while computing kk. Steady-state
// 8 outstanding LDG.128 per warp (~2 kk of latency cover).
// ---------------------------------------------------------------------------
__device__ __forceinline__ void gemm_stream_q(ull acc[4][4],
                                              const float4* __restrict__ T,
                                              float4 wA[4], float4 wB[4],
                                              int q, int l,
                                              const float* s_h,
                                              const float* s_in)
{
    const float4* Tp = T + ((q * 16) << 7) + l;

    #pragma unroll
    for (int kk = 0; kk < 16; kk++) {
        float4 wC[4];
        if (kk < 14) {
            #pragma unroll
            for (int jj = 0; jj < 4; jj++)
                wC[jj] = __ldg(Tp + (kk + 2) * 128 + jj * 32);
        }
        const int k0 = (q * 16 + kk) * 2;
        ulonglong2 hA0 = *(const ulonglong2*)(s_h  + k0 * 8);
        ulonglong2 hB0 = *(const ulonglong2*)(s_h  + k0 * 8 + 4);
        ulonglong2 xA0 = *(const ulonglong2*)(s_in + k0 * 8);
        ulonglong2 xB0 = *(const ulonglong2*)(s_in + k0 * 8 + 4);
        ulonglong2 hA1 = *(const ulonglong2*)(s_h  + k0 * 8 + 8);
        ulonglong2 hB1 = *(const ulonglong2*)(s_h  + k0 * 8 + 12);
        ulonglong2 xA1 = *(const ulonglong2*)(s_in + k0 * 8 + 8);
        ulonglong2 xB1 = *(const ulonglong2*)(s_in + k0 * 8 + 12);
        #pragma unroll
        for (int jj = 0; jj < 4; jj++) {
            float4 w = wA[jj];
            ull w0 = pack_dup(w.x), c0 = pack_dup(w.y);
            FMA2(acc[jj][0], w0, hA0.x); FMA2(acc[jj][1], w0, hA0.y);
            FMA2(acc[jj][2], w0, hB0.x); FMA2(acc[jj][3], w0, hB0.y);
            FMA2(acc[jj][0], c0, xA0.x); FMA2(acc[jj][1], c0, xA0.y);
            FMA2(acc[jj][2], c0, xB0.x); FMA2(acc[jj][3], c0, xB0.y);
            ull w1 = pack_dup(w.z), c1 = pack_dup(w.w);
            FMA2(acc[jj][0], w1, hA1.x); FMA2(acc[jj][1], w1, hA1.y);
            FMA2(acc[jj][2], w1, hB1.x); FMA2(acc[jj][3], w1, hB1.y);
            FMA2(acc[jj][0], c1, xA1.x); FMA2(acc[jj][1], c1, xA1.y);
            FMA2(acc[jj][2], c1, xB1.x); FMA2(acc[jj][3], c1, xB1.y);
        }
        #pragma unroll
        for (int jj = 0; jj < 4; jj++) { wA[jj] = wB[jj]; wB[jj] = wC[jj]; }
    }
}

// N2 gate (h-only, smem-resident table).
__device__ __forceinline__ void gemm_n2_q(ull acc[4][4],
                                          const float2* __restrict__ sT,
                                          int q, int l, const float* s_h)
{
    #pragma unroll
    for (int i = 0; i < 16; i++) {
        const int kk = q * 16 + i;
        const int k0 = kk * 2;
        ulonglong2 hA0 = *(const ulonglong2*)(s_h + k0 * 8);
        ulonglong2 hB0 = *(const ulonglong2*)(s_h + k0 * 8 + 4);
        ulonglong2 hA1 = *(const ulonglong2*)(s_h + k0 * 8 + 8);
        ulonglong2 hB1 = *(const ulonglong2*)(s_h + k0 * 8 + 12);
        #pragma unroll
        for (int jj = 0; jj < 4; jj++) {
            float2 w = sT[(kk << 7) + l + 32 * jj];
            ull w0 = pack_dup(w.x), w1 = pack_dup(w.y);
            FMA2(acc[jj][0], w0, hA0.x); FMA2(acc[jj][1], w0, hA0.y);
            FMA2(acc[jj][2], w0, hB0.x); FMA2(acc[jj][3], w0, hB0.y);
            FMA2(acc[jj][0], w1, hA1.x); FMA2(acc[jj][1], w1, hA1.y);
            FMA2(acc[jj][2], w1, hB1.x); FMA2(acc[jj][3], w1, hB1.y);
        }
    }
}

// ---------------------------------------------------------------------------
// Main kernel: 128 blocks x 512 threads, 8 batch rows per block.
// Warp wid: gate g = wid>>2, K-quarter q = wid&3 (one warp of each gate per
// SMSP). Lane l covers j = l+32*jj. Partials exchanged in smem layout
// [gate][j][pair][q] with stride 17 ull (conflict-free scalar LDS);
// thread (jr = tid&127, pr = tid>>7) owns h row-pair (jr, rows 2pr,2pr+1).
// ---------------------------------------------------------------------------
__global__ __launch_bounds__(512, 1)
void grud_main_kernel(const float* __restrict__ tp_pred,
                      const float* __restrict__ X,
                      const float* __restrict__ tp_true,
                      const float* __restrict__ mask,
                      const float* __restrict__ Wh_dec,
                      const float* __restrict__ bh_dec,
                      const float* __restrict__ Wx_dec,
                      const float* __restrict__ bx_dec,
                      const float* __restrict__ b_ih,
                      const float* __restrict__ b_hh,
                      const float* __restrict__ Wp,
                      const float* __restrict__ bp,
                      float* __restrict__ out)
{
    extern __shared__ float smem[];
    float2* sTN2  = (float2*)(smem + OFF_TN2);
    float*  s_h   = smem + OFF_SH;
    float*  s_in  = smem + OFF_SIN;
    ull*    s_part = (ull*)(smem + OFF_PART);
    float*  s_dt  = smem + OFF_SDT;
    float*  s_bias = smem + OFF_BIAS;

    const int tid = threadIdx.x;
    const int wid = tid >> 5, l = tid & 31;
    const int g   = wid >> 2, q = wid & 3;
    const int jr  = tid & 127, pr = tid >> 7;
    const int b0  = blockIdx.x * 8;

    // ---- stage N2 table ----
    for (int i = tid; i < 64 * 128; i += 512) sTN2[i] = g_WN2p[i];

    // ---- biases: s_bias[gate*128 + j] ----
    {
        int bg = tid >> 7, bj = tid & 127;
        float ub;
        if      (bg == 0) ub = b_ih[bj]       + b_hh[bj];
        else if (bg == 1) ub = b_ih[128 + bj] + b_hh[128 + bj];
        else if (bg == 2) ub = b_ih[256 + bj];
        else              ub = b_hh[256 + bj];
        s_bias[bg * 128 + bj] = ub;
    }

    // ---- decay constants for own j (jr) ----
    float S = 0.0f;
    #pragma unroll 8
    for (int n = 0; n < NF; n++) S += Wh_dec[jr * NF + n];
    const float bh = bh_dec[jr];

    // ---- feature slot: one (row, feature) per thread ----
    const int rf = tid >> 6;          // 0..7
    const int nf = tid & 63;
    const float wxd = Wx_dec[nf * 64 + nf];
    const float bx  = bx_dec[nf];
    const float* Xp = X    + (size_t)(b0 + rf) * LTRUE * NF + nf;
    const float* Mp = mask + (size_t)(b0 + rf) * LTRUE * NF + nf;

    float sum = 0.0f, cnt = (float)LPRED;
    for (int t = 0; t < LTRUE; t++) {
        float m = Mp[t * NF], x = Xp[t * NF];
        sum += x * (1.0f - m);  cnt += 1.0f - m;
    }
    const float mu = sum / fmaxf(cnt, 1.0f);
    float xl = Xp[0];                 // LOCF state

    // ---- dt table ----
    for (int it = tid; it < 8 * LALL; it += 512) {
        int r = it / LALL, t = it % LALL;
        int b = b0 + r;
        float d = 0.0f;
        if (t > 0) {
            float a = (t     < LTRUE) ? tp_true[b * LTRUE + t]
                                      : tp_pred[b * LPRED + (t - LTRUE)];
            float p = (t - 1 < LTRUE) ? tp_true[b * LTRUE + (t - 1)]
                                      : tp_pred[b * LPRED + (t - 1 - LTRUE)];
            d = a - p;
        }
        s_dt[r * LALL + t] = d;
    }

    ull h = 0ull;                     // own row pair (jr; rows 2pr, 2pr+1)
    float xv_buf = xl;                // X[t=0] prefetch (== Xp[0])
    float mv_buf = Mp[0];
    __syncthreads();

    for (int t = 0; t < LALL; t++) {
        // ======== phase A: feature slot + decay own pair ========
        {
            float xv = (t < LTRUE) ? xv_buf : 0.0f;
            float mv = (t < LTRUE) ? mv_buf : 0.0f;
            // prefetch t+1 (in flight across S1 + GEMM)
            if (t + 1 < LTRUE) {
                xv_buf = Xp[(t + 1) * NF];
                mv_buf = Mp[(t + 1) * NF];
            }
            float d  = s_dt[rf * LALL + t];
            float gx = __expf(-fmaxf(fmaf(d, wxd, bx), 0.0f));
            xl = (mv != 0.0f) ? xl : xv;
            float xh = gx * xl + (1.0f - gx) * mu;
            float xi = mv * xv + (1.0f - mv) * xh;
            s_in[nf * 8 + rf]        = xi;
            s_in[(64 + nf) * 8 + rf] = mv;
        }
        {
            float d0 = s_dt[(2 * pr    ) * LALL + t];
            float d1 = s_dt[(2 * pr + 1) * LALL + t];
            float gh0 = __expf(-fmaxf(fmaf(d0, S, bh), 0.0f));
            float gh1 = __expf(-fmaxf(fmaf(d1, S, bh), 0.0f));
            h = mul2(h, pack_pair(gh0, gh1));
            *(ull*)(s_h + jr * 8 + 2 * pr) = h;
            if (t >= LTRUE) {
                int tt = t - LTRUE;
                float f0, f1; unpack2(h, f0, f1);
                g_rep[((size_t)(b0 + 2 * pr    ) * LPRED + tt) * HID + jr] = f0;
                g_rep[((size_t)(b0 + 2 * pr + 1) * LPRED + tt) * HID + jr] = f1;
            }
        }

        // ---- hoisted weight prefetch (kk=0 AND kk=1) for streamed gates ----
        float4 wA[4], wB[4];
        if (g < 3) {
            const float4* T = (g == 0) ? g_WRp : (g == 1) ? g_WZp : g_WN1p;
            const float4* Tp = T + ((q * 16) << 7) + l;
            #pragma unroll
            for (int jj = 0; jj < 4; jj++) wA[jj] = __ldg(Tp + jj * 32);
            #pragma unroll
            for (int jj = 0; jj < 4; jj++) wB[jj] = __ldg(Tp + 128 + jj * 32);
        }
        __syncthreads();   // S1

        // ======== phase B: K-quarter GEMM per warp ========
        {
            ull acc[4][4];
            #pragma unroll
            for (int jj = 0; jj < 4; jj++)
                #pragma unroll
                for (int p = 0; p < 4; p++) acc[jj][p] = 0ull;

            if (g < 3) {
                const float4* T = (g == 0) ? g_WRp : (g == 1) ? g_WZp : g_WN1p;
                gemm_stream_q(acc, T, wA, wB, q, l, s_h, s_in);
            } else {
                gemm_n2_q(acc, sTN2, q, l, s_h);
            }
            // layout [gate][j][pair][q], stride 17 ull per j (conflict-free)
            #pragma unroll
            for (int jj = 0; jj < 4; jj++) {
                int jdx = l + 32 * jj;
                #pragma unroll
                for (int p = 0; p < 4; p++)
                    s_part[g * PSTRIDE + jdx * 17 + p * 4 + q] = acc[jj][p];
            }
        }
        __syncthreads();   // S2

        // ======== phase C: reduce partials + activation (all threads) ========
        {
            const int base = jr * 17 + pr * 4;
            ull sR = 0ull, sZ = 0ull, sN1 = 0ull, sN2 = 0ull;
            #pragma unroll
            for (int qq = 0; qq < 4; qq++) {
                sR  = add2(sR,  s_part[0 * PSTRIDE + base + qq]);
                sZ  = add2(sZ,  s_part[1 * PSTRIDE + base + qq]);
                sN1 = add2(sN1, s_part[2 * PSTRIDE + base + qq]);
                sN2 = add2(sN2, s_part[3 * PSTRIDE + base + qq]);
            }
            sR  = add2(sR,  pack_dup(s_bias[jr]));
            sZ  = add2(sZ,  pack_dup(s_bias[128 + jr]));
            sN1 = add2(sN1, pack_dup(s_bias[256 + jr]));
            sN2 = add2(sN2, pack_dup(s_bias[384 + jr]));

            float ra, rb, za, zb, n1x, n1y, n2x, n2y, hx, hy;
            unpack2(sR, ra, rb);
            unpack2(sZ, za, zb);
            unpack2(sN1, n1x, n1y);
            unpack2(sN2, n2x, n2y);
            unpack2(h, hx, hy);
            float rg0 = 1.0f / (1.0f + __expf(-ra));
            float rg1 = 1.0f / (1.0f + __expf(-rb));
            float zg0 = 1.0f / (1.0f + __expf(-za));
            float zg1 = 1.0f / (1.0f + __expf(-zb));
            float p0  = fmaf(rg0, n2x, n1x);
            float p1  = fmaf(rg1, n2y, n1y);
            float ng0 = 1.0f - 2.0f / (1.0f + __expf(2.0f * p0));
            float ng1 = 1.0f - 2.0f / (1.0f + __expf(2.0f * p1));
            float h0  = (1.0f - zg0) * ng0 + zg0 * hx;
            float h1  = (1.0f - zg1) * ng1 + zg1 * hy;
            h = pack_pair(h0, h1);
        }
    }

    // ======== fused projection: out = rep @ Wp^T + bp (own 8 rows) ========
    __syncthreads();                  // recurrent loop done; tables dead
    {
        const float4* rep4 = (const float4*)(g_rep + (size_t)b0 * LPRED * HID);
        float4* sRep4 = (float4*)(smem + OFFP_REP);
        for (int i = tid; i < 8 * LPRED * HID / 4; i += 512)
            sRep4[i] = rep4[i];
        for (int i = tid; i < 64 * 128; i += 512) {
            int n = i >> 7, jj = i & 127;
            smem[OFFP_WP + n * 129 + jj] = Wp[i];
        }
        if (tid < 64) smem[OFFP_BP + tid] = bp[tid];
    }
    __syncthreads();
    #pragma unroll 1
    for (int qq = 0; qq < 24; qq++) {
        int o   = tid + 512 * qq;             // 0..12287
        int row = o / 1536;
        int rem = o - row * 1536;
        int tp  = rem >> 6, n = rem & 63;
        float acc = smem[OFFP_BP + n];
        const float* rp = smem + OFFP_REP + (row * LPRED + tp) * HID;
        const float* wp = smem + OFFP_WP + n * 129;
        #pragma unroll 8
        for (int jj = 0; jj < 128; jj++)
            acc = fmaf(rp[jj], wp[jj], acc);
        out[((size_t)(b0 + row) * LPRED + tp) * 64 + n] = acc;
    }
}

// ---------------------------------------------------------------------------
extern "C" void kernel_launch(void* const* d_in, const int* in_sizes, int n_in,
                              void* d_out, int out_size)
{
    const float* tp_pred = (const float*)d_in[0];
    const float* X       = (const float*)d_in[1];
    const float* tp_true = (const float*)d_in[2];
    const float* mask    = (const float*)d_in[3];
    const float* Wh_dec  = (const float*)d_in[4];
    const float* bh_dec  = (const float*)d_in[5];
    const float* Wx_dec  = (const float*)d_in[6];
    const float* bx_dec  = (const float*)d_in[7];
    const float* W_ih    = (const float*)d_in[8];
    const float* W_hh    = (const float*)d_in[9];
    const float* b_ih    = (const float*)d_in[10];
    const float* b_hh    = (const float*)d_in[11];
    const float* Wp      = (const float*)d_in[12];
    const float* bp      = (const float*)d_in[13];
    float* out = (float*)d_out;

    cudaFuncSetAttribute(grud_main_kernel,
                         cudaFuncAttributeMaxDynamicSharedMemorySize,
                         SMEM_BYTES);

    grud_prep_kernel<<<32, 256>>>(W_ih, W_hh);
    grud_main_kernel<<<BATCH / 8, 512, SMEM_BYTES>>>(
        tp_pred, X, tp_true, mask,
        Wh_dec, bh_dec, Wx_dec, bx_dec, b_ih, b_hh,
        Wp, bp, out);
}